// round 5
// baseline (speedup 1.0000x reference)
#include <cuda_runtime.h>

#define NN 100000
#define NE 3200000
#define NG 4096
#define NRL 5
#define NK (NN*NRL)   // 500000 segments
#define HID 32

// ---------------- scratch (static device globals; no allocation) ----------------
__device__ int   g_cnt[NK];
__device__ int   g_off[NK];
__device__ int   g_cur[NK];
__device__ float g_inv[NK];
__device__ int   g_ssrc[NE];
__device__ int   g_bsum[512];
__device__ int   g_bsumex[512];
__device__ float g_h[(long)NN*128];

// ---------------- sort / CSR build ----------------
__global__ void k_zero() {
    int i = blockIdx.x * blockDim.x + threadIdx.x;
    if (i < NK) g_cnt[i] = 0;
}

__global__ void k_build(const int* __restrict__ ei, const int* __restrict__ et) {
    int e = blockIdx.x * blockDim.x + threadIdx.x;
    if (e >= NE) return;
    int d = ei[NE + e];
    int t = et[e];
    atomicAdd(&g_cnt[d * NRL + t], 1);
}

__global__ void k_scanA() {
    __shared__ int sh[1024];
    int i = blockIdx.x * 1024 + threadIdx.x;
    int v = (i < NK) ? g_cnt[i] : 0;
    sh[threadIdx.x] = v;
    __syncthreads();
    for (int o = 1; o < 1024; o <<= 1) {
        int t = (threadIdx.x >= o) ? sh[threadIdx.x - o] : 0;
        __syncthreads();
        sh[threadIdx.x] += t;
        __syncthreads();
    }
    if (i < NK) g_off[i] = sh[threadIdx.x] - v;   // exclusive
    if (threadIdx.x == 1023) g_bsum[blockIdx.x] = sh[1023];
}

__global__ void k_scanB(int nb) {
    __shared__ int sh[512];
    int v = (threadIdx.x < nb) ? g_bsum[threadIdx.x] : 0;
    sh[threadIdx.x] = v;
    __syncthreads();
    for (int o = 1; o < 512; o <<= 1) {
        int t = (threadIdx.x >= o) ? sh[threadIdx.x - o] : 0;
        __syncthreads();
        sh[threadIdx.x] += t;
        __syncthreads();
    }
    g_bsumex[threadIdx.x] = sh[threadIdx.x] - v;
}

__global__ void k_scanC() {
    int i = blockIdx.x * blockDim.x + threadIdx.x;
    if (i >= NK) return;
    int o = g_off[i] + g_bsumex[i >> 10];
    g_off[i] = o;
    g_cur[i] = o;
    int c = g_cnt[i];
    g_inv[i] = 1.0f / (float)(c > 0 ? c : 1);
}

__global__ void k_scatter(const int* __restrict__ ei, const int* __restrict__ et) {
    int e = blockIdx.x * blockDim.x + threadIdx.x;
    if (e >= NE) return;
    int s = ei[e];
    int d = ei[NE + e];
    int t = et[e];
    int k = d * NRL + t;
    int p = atomicAdd(&g_cur[k], 1);
    g_ssrc[p] = s;
}

// ---------------- fused RGCN layer (IN_C = 32), two-phase, 64 nodes/block ------
// Phase A: 8 warps x 8 nodes gather per-basis aggregates -> Ash[64][164]
//          row layout: [0:128) = aggB (4 basis x 32 feat), [128:160) = x self
// Phase B: warp w computes nodes w*8..w*8+7, output = lane; W chunk (32 rows)
//          held in registers, amortized over 8 nodes.
#define ROWPAD 164
__global__ void __launch_bounds__(256) k_layer32(
    int xoff,
    const float* __restrict__ basis, const float* __restrict__ comp,
    const float* __restrict__ root, const float* __restrict__ bias,
    int yoff)
{
    extern __shared__ float sm[];
    float* Ash = sm;                       // 64 * 164
    float* Wsm = sm + 64 * ROWPAD;         // 160 * 32
    float* bsm = Wsm + 160 * 32;           // 32
    float* csh = bsm + 32;                 // 20

    int tid = threadIdx.x, w = tid >> 5, lane = tid & 31;
    for (int j = tid; j < 128 * 32; j += 256) Wsm[j] = basis[j];
    for (int j = tid; j < 32 * 32; j += 256) Wsm[128 * 32 + j] = root[j];
    if (tid < NRL * 4) csh[tid] = comp[tid];
    if (tid < 32) bsm[tid] = bias[tid];
    __syncthreads();

    const float* __restrict__ X = g_h + xoff + lane;   // per-lane feature column

    // ---- Phase A: gather ----
    int nbase = blockIdx.x * 64;
    for (int ni = 0; ni < 8; ni++) {
        int n = nbase + w * 8 + ni;
        if (n >= NN) break;   // uniform across warp
        float a0 = 0.f, a1 = 0.f, a2 = 0.f, a3 = 0.f;
        int e0 = g_off[n * NRL];
        #pragma unroll
        for (int r = 0; r < NRL; r++) {
            int seg = n * NRL + r;
            int e1 = (seg == NK - 1) ? NE : g_off[seg + 1];
            float s0 = 0.f, s1 = 0.f, s2 = 0.f, s3 = 0.f;
            int e = e0;
            for (; e + 3 < e1; e += 4) {
                int ia = g_ssrc[e + 0];
                int ib = g_ssrc[e + 1];
                int ic = g_ssrc[e + 2];
                int id = g_ssrc[e + 3];
                s0 += X[ia * 128];
                s1 += X[ib * 128];
                s2 += X[ic * 128];
                s3 += X[id * 128];
            }
            for (; e < e1; e++) s0 += X[g_ssrc[e] * 128];
            e0 = e1;
            float iv = g_inv[seg] * ((s0 + s1) + (s2 + s3));
            a0 = fmaf(csh[r * 4 + 0], iv, a0);
            a1 = fmaf(csh[r * 4 + 1], iv, a1);
            a2 = fmaf(csh[r * 4 + 2], iv, a2);
            a3 = fmaf(csh[r * 4 + 3], iv, a3);
        }
        float* row = Ash + (w * 8 + ni) * ROWPAD;
        row[0 * 32 + lane] = a0;
        row[1 * 32 + lane] = a1;
        row[2 * 32 + lane] = a2;
        row[3 * 32 + lane] = a3;
        row[128 + lane]    = X[n * 128];
    }
    __syncthreads();

    // ---- Phase B: transform (warp w -> nodes w*8..w*8+7, output col = lane) ----
    float acc[8];
    float bb = bsm[lane];
    #pragma unroll
    for (int c = 0; c < 8; c++) acc[c] = bb;

    #pragma unroll
    for (int chunk = 0; chunk < 5; chunk++) {
        float wreg[32];
        #pragma unroll
        for (int k = 0; k < 32; k++)
            wreg[k] = Wsm[(chunk * 32 + k) * 32 + lane];
        #pragma unroll
        for (int c = 0; c < 8; c++) {
            const float4* arow = (const float4*)(Ash + (w * 8 + c) * ROWPAD + chunk * 32);
            #pragma unroll
            for (int jv = 0; jv < 8; jv++) {
                float4 av = arow[jv];
                acc[c] = fmaf(av.x, wreg[jv * 4 + 0], acc[c]);
                acc[c] = fmaf(av.y, wreg[jv * 4 + 1], acc[c]);
                acc[c] = fmaf(av.z, wreg[jv * 4 + 2], acc[c]);
                acc[c] = fmaf(av.w, wreg[jv * 4 + 3], acc[c]);
            }
        }
    }
    #pragma unroll
    for (int c = 0; c < 8; c++) {
        int n = nbase + w * 8 + c;
        if (n < NN)
            g_h[(long)n * 128 + yoff + lane] = tanhf(acc[c]);
    }
}

// ---------------- layer 0 (IN_C = 4): 8 edges x 4 features across the warp -----
__global__ void __launch_bounds__(256) k_layer0(
    const float* __restrict__ x,
    const float* __restrict__ basis, const float* __restrict__ comp,
    const float* __restrict__ root, const float* __restrict__ bias)
{
    const int IN_C = 4;
    const int WPB = 8;
    const int NPW = 8;
    __shared__ float Wsh[5 * IN_C * 32];
    __shared__ float csh[NRL * 4];
    __shared__ float bsh[32];
    __shared__ float Ash[WPB][5 * IN_C];

    int tid = threadIdx.x, w = tid >> 5, lane = tid & 31;
    for (int j = tid; j < 4 * IN_C * 32; j += 256) Wsh[j] = basis[j];
    if (tid < IN_C * 32) Wsh[4 * IN_C * 32 + tid] = root[tid];
    if (tid < NRL * 4) csh[tid] = comp[tid];
    if (tid < 32) bsh[tid] = bias[tid];
    __syncthreads();

    int sub  = lane >> 2;   // 0..7 edge subgroup
    int feat = lane & 3;    // 0..3 feature

    int nbase = (blockIdx.x * WPB + w) * NPW;
    for (int ni = 0; ni < NPW; ni++) {
        int n = nbase + ni;
        if (n >= NN) break;   // uniform across warp
        float a0 = 0.f, a1 = 0.f, a2 = 0.f, a3 = 0.f;
        int e0 = g_off[n * NRL];
        #pragma unroll
        for (int r = 0; r < NRL; r++) {
            int seg = n * NRL + r;
            int e1 = (seg == NK - 1) ? NE : g_off[seg + 1];
            float sum = 0.f;
            for (int e = e0 + sub; e < e1; e += 8) {
                int s = g_ssrc[e];
                sum += x[s * 4 + feat];
            }
            e0 = e1;
            sum += __shfl_down_sync(0xffffffffu, sum, 16);
            sum += __shfl_down_sync(0xffffffffu, sum, 8);
            sum += __shfl_down_sync(0xffffffffu, sum, 4);
            if (lane < 4) {
                float iv = g_inv[seg] * sum;
                a0 = fmaf(csh[r * 4 + 0], iv, a0);
                a1 = fmaf(csh[r * 4 + 1], iv, a1);
                a2 = fmaf(csh[r * 4 + 2], iv, a2);
                a3 = fmaf(csh[r * 4 + 3], iv, a3);
            }
        }
        if (lane < 4) {
            Ash[w][0 * IN_C + lane] = a0;
            Ash[w][1 * IN_C + lane] = a1;
            Ash[w][2 * IN_C + lane] = a2;
            Ash[w][3 * IN_C + lane] = a3;
            Ash[w][4 * IN_C + lane] = x[n * 4 + lane];
        }
        __syncwarp();
        float acc = bsh[lane];
        #pragma unroll
        for (int j = 0; j < 5 * IN_C; j++)
            acc = fmaf(Ash[w][j], Wsh[j * 32 + lane], acc);
        g_h[(long)n * 128 + lane] = tanhf(acc);
        __syncwarp();
    }
}

// ---------------- MLP readout ----------------
__global__ void __launch_bounds__(128) k_mlp(
    const int* __restrict__ uidx, const int* __restrict__ iidx,
    const float* __restrict__ w1, const float* __restrict__ b1,
    const float* __restrict__ w2, const float* __restrict__ b2,
    float* __restrict__ out)
{
    const int GPB = 8;
    __shared__ float gsh[GPB * 256];
    __shared__ float red[128];
    int tid = threadIdx.x;
    int gbase = blockIdx.x * GPB;

    for (int idx = tid; idx < GPB * 256; idx += 128) {
        int gi = idx >> 8, k = idx & 255;
        int g = gbase + gi;
        int n = (k < 128) ? uidx[g] : iidx[g];
        gsh[idx] = g_h[(long)n * 128 + (k & 127)];
    }
    __syncthreads();

    float acc[GPB];
    float bb = b1[tid];
    #pragma unroll
    for (int gi = 0; gi < GPB; gi++) acc[gi] = bb;

    for (int k = 0; k < 256; k++) {
        float wv = w1[k * 128 + tid];
        #pragma unroll
        for (int gi = 0; gi < GPB; gi++)
            acc[gi] = fmaf(gsh[gi * 256 + k], wv, acc[gi]);
    }

    float w2v = w2[tid];
    float b2v = b2[0];
    #pragma unroll
    for (int gi = 0; gi < GPB; gi++) {
        float z = fmaxf(acc[gi], 0.f) * w2v;
        red[tid] = z;
        __syncthreads();
        for (int o = 64; o > 0; o >>= 1) {
            if (tid < o) red[tid] += red[tid + o];
            __syncthreads();
        }
        if (tid == 0) out[gbase + gi] = red[0] + b2v;
        __syncthreads();
    }
}

// ---------------- launcher ----------------
extern "C" void kernel_launch(void* const* d_in, const int* in_sizes, int n_in,
                              void* d_out, int out_size)
{
    const float* x  = (const float*)d_in[0];
    const int*   ei = (const int*)d_in[1];
    const int*   et = (const int*)d_in[2];
    const int*   ui = (const int*)d_in[3];
    const int*   ii = (const int*)d_in[4];
    const float* basis[4] = {(const float*)d_in[5],  (const float*)d_in[9],
                             (const float*)d_in[13], (const float*)d_in[17]};
    const float* comp[4]  = {(const float*)d_in[6],  (const float*)d_in[10],
                             (const float*)d_in[14], (const float*)d_in[18]};
    const float* root[4]  = {(const float*)d_in[7],  (const float*)d_in[11],
                             (const float*)d_in[15], (const float*)d_in[19]};
    const float* bias[4]  = {(const float*)d_in[8],  (const float*)d_in[12],
                             (const float*)d_in[16], (const float*)d_in[20]};
    const float* w1 = (const float*)d_in[21];
    const float* b1 = (const float*)d_in[22];
    const float* w2 = (const float*)d_in[23];
    const float* b2 = (const float*)d_in[24];
    float* out = (float*)d_out;

    // build CSR by (dst,rel) via counting sort
    k_zero<<<(NK + 255) / 256, 256>>>();
    k_build<<<(NE + 255) / 256, 256>>>(ei, et);
    k_scanA<<<(NK + 1023) / 1024, 1024>>>();
    k_scanB<<<1, 512>>>((NK + 1023) / 1024);
    k_scanC<<<(NK + 255) / 256, 256>>>();
    k_scatter<<<(NE + 255) / 256, 256>>>(ei, et);

    // layer 0: input x [N,4]
    int lblocks0 = (NN + 63) / 64;
    k_layer0<<<lblocks0, 256>>>(x, basis[0], comp[0], root[0], bias[0]);

    // layers 1..3: two-phase, 64 nodes/block, dynamic smem
    const int SMEM = (64 * ROWPAD + 160 * 32 + 32 + 20) * sizeof(float);
    static int attr_set = 0;
    if (!attr_set) {
        cudaFuncSetAttribute(k_layer32, cudaFuncAttributeMaxDynamicSharedMemorySize, SMEM);
        attr_set = 1;
    }
    int lblocks = (NN + 63) / 64;
    k_layer32<<<lblocks, 256, SMEM>>>(0,  basis[1], comp[1], root[1], bias[1], 32);
    k_layer32<<<lblocks, 256, SMEM>>>(32, basis[2], comp[2], root[2], bias[2], 64);
    k_layer32<<<lblocks, 256, SMEM>>>(64, basis[3], comp[3], root[3], bias[3], 96);

    // MLP readout
    k_mlp<<<NG / 8, 128>>>(ui, ii, w1, b1, w2, b2, out);
}

// round 6
// speedup vs baseline: 1.0510x; 1.0510x over previous
#include <cuda_runtime.h>

#define NN 100000
#define NE 3200000
#define NG 4096
#define NRL 5
#define NK (NN*NRL)   // 500000 segments
#define HID 32
#define SCAN_NB ((NK + 1023) / 1024)

// ---------------- scratch (static device globals; no allocation) ----------------
__device__ int   g_cnt[NK];
__device__ int   g_off[NK];
__device__ int   g_cur[NK];
__device__ float g_inv[NK];
__device__ int   g_ssrc[NE];
__device__ float g_h[(long)NN*128];
__device__ int   g_sflag[SCAN_NB];
__device__ int   g_sagg[SCAN_NB];
__device__ int   g_sincl[SCAN_NB];
__device__ int   g_sdone;

// ---------------- build counts ----------------
__global__ void k_build(const int* __restrict__ ei, const int* __restrict__ et) {
    int e = blockIdx.x * blockDim.x + threadIdx.x;
    if (e >= NE) return;
    int d = ei[NE + e];
    int t = et[e];
    atomicAdd(&g_cnt[d * NRL + t], 1);
}

// ---------------- single-pass scan (decoupled lookback) ----------------
// Also: computes g_inv, initializes g_cur, and zeroes g_cnt for the next
// graph replay. Flags are reset by the last-finishing block (cleaner).
__global__ void __launch_bounds__(1024) k_scan() {
    __shared__ int sh[1024];
    __shared__ int s_base;
    __shared__ int s_last;
    int b = blockIdx.x;
    int i = b * 1024 + threadIdx.x;
    int v = (i < NK) ? g_cnt[i] : 0;
    sh[threadIdx.x] = v;
    __syncthreads();
    for (int o = 1; o < 1024; o <<= 1) {
        int t = (threadIdx.x >= o) ? sh[threadIdx.x - o] : 0;
        __syncthreads();
        sh[threadIdx.x] += t;
        __syncthreads();
    }
    int incl_local = sh[threadIdx.x];
    int total = sh[1023];

    if (threadIdx.x == 0) {
        if (b == 0) {
            g_sincl[0] = total;
            __threadfence();
            atomicExch(&g_sflag[0], 2);
            s_base = 0;
        } else {
            g_sagg[b] = total;
            __threadfence();
            atomicExch(&g_sflag[b], 1);
            // lookback: only waits on LOWER block ids (scheduled earlier)
            int p = b - 1;
            int sum = 0;
            while (true) {
                int f;
                do { f = atomicAdd(&g_sflag[p], 0); } while (f == 0);
                __threadfence();
                if (f == 2) { sum += g_sincl[p]; break; }
                sum += g_sagg[p];
                p--;
            }
            s_base = sum;
            g_sincl[b] = sum + total;
            __threadfence();
            atomicExch(&g_sflag[b], 2);
        }
    }
    __syncthreads();
    int base = s_base;
    if (i < NK) {
        int o = base + incl_local - v;
        g_off[i] = o;
        g_cur[i] = o;
        g_inv[i] = 1.0f / (float)(v > 0 ? v : 1);
        g_cnt[i] = 0;   // ready for next replay's k_build
    }
    __syncthreads();
    if (threadIdx.x == 0) {
        __threadfence();
        s_last = (atomicAdd(&g_sdone, 1) == (int)gridDim.x - 1) ? 1 : 0;
    }
    __syncthreads();
    if (s_last) {
        for (int j = threadIdx.x; j < SCAN_NB; j += 1024) g_sflag[j] = 0;
        __syncthreads();
        if (threadIdx.x == 0) { __threadfence(); g_sdone = 0; }
    }
}

// ---------------- scatter (counting-sort pass 2) ----------------
__global__ void k_scatter(const int* __restrict__ ei, const int* __restrict__ et) {
    int e = blockIdx.x * blockDim.x + threadIdx.x;
    if (e >= NE) return;
    int s = ei[e];
    int d = ei[NE + e];
    int t = et[e];
    int k = d * NRL + t;
    int p = atomicAdd(&g_cur[k], 1);
    g_ssrc[p] = s;
}

// ---------------- fused RGCN layer (IN_C = 32) ----------------
// Per warp: gather 4 nodes into per-warp smem staging, then transform all 4
// with the W chunk held in registers (amortized over 4 nodes), A rows read
// as broadcast LDS.128. No block-wide barrier between gather and transform.
__global__ void __launch_bounds__(256) k_layer32(
    int xoff,
    const float* __restrict__ basis, const float* __restrict__ comp,
    const float* __restrict__ root, const float* __restrict__ bias,
    int yoff)
{
    __shared__ float Wsh[160 * 32];       // 20 KB: rows 0..127 basis, 128..159 root
    __shared__ float stage[8][4 * 160];   // 20 KB: per-warp, 4 nodes x 160
    __shared__ float csh[NRL * 4];
    __shared__ float bsh[32];

    int tid = threadIdx.x, w = tid >> 5, lane = tid & 31;
    for (int j = tid; j < 128 * 32; j += 256) Wsh[j] = basis[j];
    for (int j = tid; j < 32 * 32; j += 256) Wsh[128 * 32 + j] = root[j];
    if (tid < NRL * 4) csh[tid] = comp[tid];
    if (tid < 32) bsh[tid] = bias[tid];
    __syncthreads();

    const float* __restrict__ X = g_h + xoff + lane;   // per-lane feature column

    int nbase = (blockIdx.x * 8 + w) * 4;

    // ---- gather 4 nodes into stage ----
    #pragma unroll
    for (int c = 0; c < 4; c++) {
        int n = nbase + c;
        float a0 = 0.f, a1 = 0.f, a2 = 0.f, a3 = 0.f, self = 0.f;
        if (n < NN) {   // uniform across warp
            int e0 = g_off[n * NRL];
            #pragma unroll
            for (int r = 0; r < NRL; r++) {
                int seg = n * NRL + r;
                int e1 = (seg == NK - 1) ? NE : g_off[seg + 1];
                float s0 = 0.f, s1 = 0.f, s2 = 0.f, s3 = 0.f;
                int e = e0;
                for (; e + 3 < e1; e += 4) {
                    int ia = g_ssrc[e + 0];
                    int ib = g_ssrc[e + 1];
                    int ic = g_ssrc[e + 2];
                    int id = g_ssrc[e + 3];
                    s0 += X[ia * 128];
                    s1 += X[ib * 128];
                    s2 += X[ic * 128];
                    s3 += X[id * 128];
                }
                for (; e < e1; e++) s0 += X[g_ssrc[e] * 128];
                e0 = e1;
                float iv = g_inv[seg] * ((s0 + s1) + (s2 + s3));
                a0 = fmaf(csh[r * 4 + 0], iv, a0);
                a1 = fmaf(csh[r * 4 + 1], iv, a1);
                a2 = fmaf(csh[r * 4 + 2], iv, a2);
                a3 = fmaf(csh[r * 4 + 3], iv, a3);
            }
            self = X[n * 128];
        }
        float* row = &stage[w][c * 160];
        row[0 * 32 + lane] = a0;
        row[1 * 32 + lane] = a1;
        row[2 * 32 + lane] = a2;
        row[3 * 32 + lane] = a3;
        row[4 * 32 + lane] = self;
    }
    __syncwarp();

    // ---- transform: W chunks in registers, amortized over 4 nodes ----
    float acc[4];
    float bb = bsh[lane];
    #pragma unroll
    for (int c = 0; c < 4; c++) acc[c] = bb;

    #pragma unroll
    for (int ch = 0; ch < 5; ch++) {
        float wreg[32];
        #pragma unroll
        for (int k = 0; k < 32; k++)
            wreg[k] = Wsh[(ch * 32 + k) * 32 + lane];
        #pragma unroll
        for (int c = 0; c < 4; c++) {
            const float4* ar = (const float4*)&stage[w][c * 160 + ch * 32];
            #pragma unroll
            for (int jv = 0; jv < 8; jv++) {
                float4 av = ar[jv];
                acc[c] = fmaf(av.x, wreg[jv * 4 + 0], acc[c]);
                acc[c] = fmaf(av.y, wreg[jv * 4 + 1], acc[c]);
                acc[c] = fmaf(av.z, wreg[jv * 4 + 2], acc[c]);
                acc[c] = fmaf(av.w, wreg[jv * 4 + 3], acc[c]);
            }
        }
    }
    #pragma unroll
    for (int c = 0; c < 4; c++) {
        int n = nbase + c;
        if (n < NN)
            g_h[(long)n * 128 + yoff + lane] = tanhf(acc[c]);
    }
}

// ---------------- layer 0 (IN_C = 4): 8 edges x 4 features across the warp -----
__global__ void __launch_bounds__(256) k_layer0(
    const float* __restrict__ x,
    const float* __restrict__ basis, const float* __restrict__ comp,
    const float* __restrict__ root, const float* __restrict__ bias)
{
    const int IN_C = 4;
    const int WPB = 8;
    const int NPW = 8;
    __shared__ float Wsh[5 * IN_C * 32];
    __shared__ float csh[NRL * 4];
    __shared__ float bsh[32];
    __shared__ float Ash[WPB][5 * IN_C];

    int tid = threadIdx.x, w = tid >> 5, lane = tid & 31;
    for (int j = tid; j < 4 * IN_C * 32; j += 256) Wsh[j] = basis[j];
    if (tid < IN_C * 32) Wsh[4 * IN_C * 32 + tid] = root[tid];
    if (tid < NRL * 4) csh[tid] = comp[tid];
    if (tid < 32) bsh[tid] = bias[tid];
    __syncthreads();

    int sub  = lane >> 2;   // 0..7 edge subgroup
    int feat = lane & 3;    // 0..3 feature

    int nbase = (blockIdx.x * WPB + w) * NPW;
    for (int ni = 0; ni < NPW; ni++) {
        int n = nbase + ni;
        if (n >= NN) break;   // uniform across warp
        float a0 = 0.f, a1 = 0.f, a2 = 0.f, a3 = 0.f;
        int e0 = g_off[n * NRL];
        #pragma unroll
        for (int r = 0; r < NRL; r++) {
            int seg = n * NRL + r;
            int e1 = (seg == NK - 1) ? NE : g_off[seg + 1];
            float sum = 0.f;
            for (int e = e0 + sub; e < e1; e += 8) {
                int s = g_ssrc[e];
                sum += x[s * 4 + feat];
            }
            e0 = e1;
            sum += __shfl_down_sync(0xffffffffu, sum, 16);
            sum += __shfl_down_sync(0xffffffffu, sum, 8);
            sum += __shfl_down_sync(0xffffffffu, sum, 4);
            if (lane < 4) {
                float iv = g_inv[seg] * sum;
                a0 = fmaf(csh[r * 4 + 0], iv, a0);
                a1 = fmaf(csh[r * 4 + 1], iv, a1);
                a2 = fmaf(csh[r * 4 + 2], iv, a2);
                a3 = fmaf(csh[r * 4 + 3], iv, a3);
            }
        }
        if (lane < 4) {
            Ash[w][0 * IN_C + lane] = a0;
            Ash[w][1 * IN_C + lane] = a1;
            Ash[w][2 * IN_C + lane] = a2;
            Ash[w][3 * IN_C + lane] = a3;
            Ash[w][4 * IN_C + lane] = x[n * 4 + lane];
        }
        __syncwarp();
        float acc = bsh[lane];
        #pragma unroll
        for (int j = 0; j < 5 * IN_C; j++)
            acc = fmaf(Ash[w][j], Wsh[j * 32 + lane], acc);
        g_h[(long)n * 128 + lane] = tanhf(acc);
        __syncwarp();
    }
}

// ---------------- MLP readout ----------------
__global__ void __launch_bounds__(128) k_mlp(
    const int* __restrict__ uidx, const int* __restrict__ iidx,
    const float* __restrict__ w1, const float* __restrict__ b1,
    const float* __restrict__ w2, const float* __restrict__ b2,
    float* __restrict__ out)
{
    const int GPB = 8;
    __shared__ float gsh[GPB * 256];
    __shared__ float red[128];
    int tid = threadIdx.x;
    int gbase = blockIdx.x * GPB;

    for (int idx = tid; idx < GPB * 256; idx += 128) {
        int gi = idx >> 8, k = idx & 255;
        int g = gbase + gi;
        int n = (k < 128) ? uidx[g] : iidx[g];
        gsh[idx] = g_h[(long)n * 128 + (k & 127)];
    }
    __syncthreads();

    float acc[GPB];
    float bb = b1[tid];
    #pragma unroll
    for (int gi = 0; gi < GPB; gi++) acc[gi] = bb;

    for (int k = 0; k < 256; k++) {
        float wv = w1[k * 128 + tid];
        #pragma unroll
        for (int gi = 0; gi < GPB; gi++)
            acc[gi] = fmaf(gsh[gi * 256 + k], wv, acc[gi]);
    }

    float w2v = w2[tid];
    float b2v = b2[0];
    #pragma unroll
    for (int gi = 0; gi < GPB; gi++) {
        float z = fmaxf(acc[gi], 0.f) * w2v;
        red[tid] = z;
        __syncthreads();
        for (int o = 64; o > 0; o >>= 1) {
            if (tid < o) red[tid] += red[tid + o];
            __syncthreads();
        }
        if (tid == 0) out[gbase + gi] = red[0] + b2v;
        __syncthreads();
    }
}

// ---------------- launcher ----------------
extern "C" void kernel_launch(void* const* d_in, const int* in_sizes, int n_in,
                              void* d_out, int out_size)
{
    const float* x  = (const float*)d_in[0];
    const int*   ei = (const int*)d_in[1];
    const int*   et = (const int*)d_in[2];
    const int*   ui = (const int*)d_in[3];
    const int*   ii = (const int*)d_in[4];
    const float* basis[4] = {(const float*)d_in[5],  (const float*)d_in[9],
                             (const float*)d_in[13], (const float*)d_in[17]};
    const float* comp[4]  = {(const float*)d_in[6],  (const float*)d_in[10],
                             (const float*)d_in[14], (const float*)d_in[18]};
    const float* root[4]  = {(const float*)d_in[7],  (const float*)d_in[11],
                             (const float*)d_in[15], (const float*)d_in[19]};
    const float* bias[4]  = {(const float*)d_in[8],  (const float*)d_in[12],
                             (const float*)d_in[16], (const float*)d_in[20]};
    const float* w1 = (const float*)d_in[21];
    const float* b1 = (const float*)d_in[22];
    const float* w2 = (const float*)d_in[23];
    const float* b2 = (const float*)d_in[24];
    float* out = (float*)d_out;

    // counting sort by (dst, rel):
    // g_cnt starts zero (static init on first call, re-zeroed by k_scan each run)
    k_build<<<(NE + 255) / 256, 256>>>(ei, et);
    k_scan<<<SCAN_NB, 1024>>>();
    k_scatter<<<(NE + 255) / 256, 256>>>(ei, et);

    // layer 0: input x [N,4]
    k_layer0<<<(NN + 63) / 64, 256>>>(x, basis[0], comp[0], root[0], bias[0]);

    // layers 1..3: 32 nodes/block (8 warps x 4 nodes)
    int lblocks = (NN + 31) / 32;
    k_layer32<<<lblocks, 256>>>(0,  basis[1], comp[1], root[1], bias[1], 32);
    k_layer32<<<lblocks, 256>>>(32, basis[2], comp[2], root[2], bias[2], 64);
    k_layer32<<<lblocks, 256>>>(64, basis[3], comp[3], root[3], bias[3], 96);

    // MLP readout
    k_mlp<<<NG / 8, 128>>>(ui, ii, w1, b1, w2, b2, out);
}

// round 7
// speedup vs baseline: 1.0876x; 1.0348x over previous
#include <cuda_runtime.h>

#define NN 100000
#define NE 3200000
#define NG 4096
#define NRL 5
#define NK (NN*NRL)   // 500000 segments
#define HID 32
#define SCAN_NB ((NK + 1023) / 1024)

// ---------------- scratch (static device globals; no allocation) ----------------
__device__ int   g_cnt[NK];
__device__ int   g_off[NK];
__device__ int   g_cur[NK];
__device__ float g_inv[NK];
__device__ int   g_ssrc[NE];
__device__ float g_h[(long)NN*128];
__device__ int   g_sflag[SCAN_NB];
__device__ int   g_sagg[SCAN_NB];
__device__ int   g_sincl[SCAN_NB];
__device__ int   g_sdone;

// ---------------- build counts ----------------
__global__ void k_build(const int* __restrict__ ei, const int* __restrict__ et) {
    int e = blockIdx.x * blockDim.x + threadIdx.x;
    if (e >= NE) return;
    int d = ei[NE + e];
    int t = et[e];
    atomicAdd(&g_cnt[d * NRL + t], 1);
}

// ---------------- single-pass scan (decoupled lookback) ----------------
__global__ void __launch_bounds__(1024) k_scan() {
    __shared__ int sh[1024];
    __shared__ int s_base;
    __shared__ int s_last;
    int b = blockIdx.x;
    int i = b * 1024 + threadIdx.x;
    int v = (i < NK) ? g_cnt[i] : 0;
    sh[threadIdx.x] = v;
    __syncthreads();
    for (int o = 1; o < 1024; o <<= 1) {
        int t = (threadIdx.x >= o) ? sh[threadIdx.x - o] : 0;
        __syncthreads();
        sh[threadIdx.x] += t;
        __syncthreads();
    }
    int incl_local = sh[threadIdx.x];
    int total = sh[1023];

    if (threadIdx.x == 0) {
        if (b == 0) {
            g_sincl[0] = total;
            __threadfence();
            atomicExch(&g_sflag[0], 2);
            s_base = 0;
        } else {
            g_sagg[b] = total;
            __threadfence();
            atomicExch(&g_sflag[b], 1);
            int p = b - 1;
            int sum = 0;
            while (true) {
                int f;
                do { f = atomicAdd(&g_sflag[p], 0); } while (f == 0);
                __threadfence();
                if (f == 2) { sum += g_sincl[p]; break; }
                sum += g_sagg[p];
                p--;
            }
            s_base = sum;
            g_sincl[b] = sum + total;
            __threadfence();
            atomicExch(&g_sflag[b], 2);
        }
    }
    __syncthreads();
    int base = s_base;
    if (i < NK) {
        int o = base + incl_local - v;
        g_off[i] = o;
        g_cur[i] = o;
        g_inv[i] = 1.0f / (float)(v > 0 ? v : 1);
        g_cnt[i] = 0;   // ready for next replay's k_build
    }
    __syncthreads();
    if (threadIdx.x == 0) {
        __threadfence();
        s_last = (atomicAdd(&g_sdone, 1) == (int)gridDim.x - 1) ? 1 : 0;
    }
    __syncthreads();
    if (s_last) {
        for (int j = threadIdx.x; j < SCAN_NB; j += 1024) g_sflag[j] = 0;
        __syncthreads();
        if (threadIdx.x == 0) { __threadfence(); g_sdone = 0; }
    }
}

// ---------------- scatter (counting-sort pass 2) ----------------
__global__ void k_scatter(const int* __restrict__ ei, const int* __restrict__ et) {
    int e = blockIdx.x * blockDim.x + threadIdx.x;
    if (e >= NE) return;
    int s = ei[e];
    int d = ei[NE + e];
    int t = et[e];
    int k = d * NRL + t;
    int p = atomicAdd(&g_cur[k], 1);
    g_ssrc[p] = s;
}

// ---------------- fused RGCN layer (IN_C = 32) ----------------
// 8 warps x 8 nodes per block, processed in groups of 4:
//   gather 4 nodes -> Ash[w][4][160], then transform the group with
//   float4 broadcast A reads and W row shared across the 4 accumulators.
__global__ void __launch_bounds__(256, 4) k_layer32(
    int xoff,
    const float* __restrict__ basis, const float* __restrict__ comp,
    const float* __restrict__ root, const float* __restrict__ bias,
    int yoff)
{
    __shared__ float Wsh[160 * 32];                    // 20 KB
    __shared__ __align__(16) float Ash[8][4 * 160];    // 20 KB (8 warps x 4 nodes x 160)
    __shared__ float csh[NRL * 4];
    __shared__ float bsh[32];

    int tid = threadIdx.x, w = tid >> 5, lane = tid & 31;
    for (int j = tid; j < 128 * 32; j += 256) Wsh[j] = basis[j];
    for (int j = tid; j < 32 * 32; j += 256) Wsh[128 * 32 + j] = root[j];
    if (tid < NRL * 4) csh[tid] = comp[tid];
    if (tid < 32) bsh[tid] = bias[tid];
    __syncthreads();

    const float* __restrict__ X = g_h + xoff + lane;   // per-lane feature column

    int nwarp = (blockIdx.x * 8 + w) * 8;              // first node of this warp

    #pragma unroll
    for (int grp = 0; grp < 2; grp++) {
        int nbase = nwarp + grp * 4;

        // ---- gather 4 nodes into Ash[w] ----
        for (int c = 0; c < 4; c++) {
            int n = nbase + c;
            float a0 = 0.f, a1 = 0.f, a2 = 0.f, a3 = 0.f, self = 0.f;
            if (n < NN) {   // uniform across warp
                int e0 = g_off[n * NRL];
                #pragma unroll
                for (int r = 0; r < NRL; r++) {
                    int seg = n * NRL + r;
                    int e1 = (seg == NK - 1) ? NE : g_off[seg + 1];
                    float s0 = 0.f, s1 = 0.f, s2 = 0.f, s3 = 0.f;
                    int e = e0;
                    for (; e + 3 < e1; e += 4) {
                        int ia = g_ssrc[e + 0];
                        int ib = g_ssrc[e + 1];
                        int ic = g_ssrc[e + 2];
                        int id = g_ssrc[e + 3];
                        s0 += X[ia * 128];
                        s1 += X[ib * 128];
                        s2 += X[ic * 128];
                        s3 += X[id * 128];
                    }
                    for (; e < e1; e++) s0 += X[g_ssrc[e] * 128];
                    e0 = e1;
                    float iv = g_inv[seg] * ((s0 + s1) + (s2 + s3));
                    a0 = fmaf(csh[r * 4 + 0], iv, a0);
                    a1 = fmaf(csh[r * 4 + 1], iv, a1);
                    a2 = fmaf(csh[r * 4 + 2], iv, a2);
                    a3 = fmaf(csh[r * 4 + 3], iv, a3);
                }
                self = X[n * 128];
            }
            float* row = &Ash[w][c * 160];
            row[0 * 32 + lane] = a0;
            row[1 * 32 + lane] = a1;
            row[2 * 32 + lane] = a2;
            row[3 * 32 + lane] = a3;
            row[4 * 32 + lane] = self;
        }
        __syncwarp();

        // ---- transform group of 4: A via float4 broadcast, W shared ----
        float bb = bsh[lane];
        float acc0 = bb, acc1 = bb, acc2 = bb, acc3 = bb;
        const float4* A0 = (const float4*)&Ash[w][0 * 160];
        const float4* A1 = (const float4*)&Ash[w][1 * 160];
        const float4* A2 = (const float4*)&Ash[w][2 * 160];
        const float4* A3 = (const float4*)&Ash[w][3 * 160];
        #pragma unroll 8
        for (int jv = 0; jv < 40; jv++) {
            float4 u0 = A0[jv];
            float4 u1 = A1[jv];
            float4 u2 = A2[jv];
            float4 u3 = A3[jv];
            const float* wp = &Wsh[jv * 128 + lane];
            float w0 = wp[0], w1 = wp[32], w2 = wp[64], w3 = wp[96];
            acc0 = fmaf(u0.x, w0, acc0); acc1 = fmaf(u1.x, w0, acc1);
            acc2 = fmaf(u2.x, w0, acc2); acc3 = fmaf(u3.x, w0, acc3);
            acc0 = fmaf(u0.y, w1, acc0); acc1 = fmaf(u1.y, w1, acc1);
            acc2 = fmaf(u2.y, w1, acc2); acc3 = fmaf(u3.y, w1, acc3);
            acc0 = fmaf(u0.z, w2, acc0); acc1 = fmaf(u1.z, w2, acc1);
            acc2 = fmaf(u2.z, w2, acc2); acc3 = fmaf(u3.z, w2, acc3);
            acc0 = fmaf(u0.w, w3, acc0); acc1 = fmaf(u1.w, w3, acc1);
            acc2 = fmaf(u2.w, w3, acc2); acc3 = fmaf(u3.w, w3, acc3);
        }
        if (nbase + 0 < NN) g_h[(long)(nbase + 0) * 128 + yoff + lane] = tanhf(acc0);
        if (nbase + 1 < NN) g_h[(long)(nbase + 1) * 128 + yoff + lane] = tanhf(acc1);
        if (nbase + 2 < NN) g_h[(long)(nbase + 2) * 128 + yoff + lane] = tanhf(acc2);
        if (nbase + 3 < NN) g_h[(long)(nbase + 3) * 128 + yoff + lane] = tanhf(acc3);
        __syncwarp();
    }
}

// ---------------- layer 0 (IN_C = 4): 8 edges x 4 features across the warp -----
__global__ void __launch_bounds__(256) k_layer0(
    const float* __restrict__ x,
    const float* __restrict__ basis, const float* __restrict__ comp,
    const float* __restrict__ root, const float* __restrict__ bias)
{
    const int IN_C = 4;
    const int WPB = 8;
    const int NPW = 8;
    __shared__ float Wsh[5 * IN_C * 32];
    __shared__ float csh[NRL * 4];
    __shared__ float bsh[32];
    __shared__ float Ash[WPB][5 * IN_C];

    int tid = threadIdx.x, w = tid >> 5, lane = tid & 31;
    for (int j = tid; j < 4 * IN_C * 32; j += 256) Wsh[j] = basis[j];
    if (tid < IN_C * 32) Wsh[4 * IN_C * 32 + tid] = root[tid];
    if (tid < NRL * 4) csh[tid] = comp[tid];
    if (tid < 32) bsh[tid] = bias[tid];
    __syncthreads();

    int sub  = lane >> 2;   // 0..7 edge subgroup
    int feat = lane & 3;    // 0..3 feature

    int nbase = (blockIdx.x * WPB + w) * NPW;
    for (int ni = 0; ni < NPW; ni++) {
        int n = nbase + ni;
        if (n >= NN) break;   // uniform across warp
        float a0 = 0.f, a1 = 0.f, a2 = 0.f, a3 = 0.f;
        int e0 = g_off[n * NRL];
        #pragma unroll
        for (int r = 0; r < NRL; r++) {
            int seg = n * NRL + r;
            int e1 = (seg == NK - 1) ? NE : g_off[seg + 1];
            float sum = 0.f;
            for (int e = e0 + sub; e < e1; e += 8) {
                int s = g_ssrc[e];
                sum += x[s * 4 + feat];
            }
            e0 = e1;
            sum += __shfl_down_sync(0xffffffffu, sum, 16);
            sum += __shfl_down_sync(0xffffffffu, sum, 8);
            sum += __shfl_down_sync(0xffffffffu, sum, 4);
            if (lane < 4) {
                float iv = g_inv[seg] * sum;
                a0 = fmaf(csh[r * 4 + 0], iv, a0);
                a1 = fmaf(csh[r * 4 + 1], iv, a1);
                a2 = fmaf(csh[r * 4 + 2], iv, a2);
                a3 = fmaf(csh[r * 4 + 3], iv, a3);
            }
        }
        if (lane < 4) {
            Ash[w][0 * IN_C + lane] = a0;
            Ash[w][1 * IN_C + lane] = a1;
            Ash[w][2 * IN_C + lane] = a2;
            Ash[w][3 * IN_C + lane] = a3;
            Ash[w][4 * IN_C + lane] = x[n * 4 + lane];
        }
        __syncwarp();
        float acc = bsh[lane];
        #pragma unroll
        for (int j = 0; j < 5 * IN_C; j++)
            acc = fmaf(Ash[w][j], Wsh[j * 32 + lane], acc);
        g_h[(long)n * 128 + lane] = tanhf(acc);
        __syncwarp();
    }
}

// ---------------- MLP readout ----------------
__global__ void __launch_bounds__(128) k_mlp(
    const int* __restrict__ uidx, const int* __restrict__ iidx,
    const float* __restrict__ w1, const float* __restrict__ b1,
    const float* __restrict__ w2, const float* __restrict__ b2,
    float* __restrict__ out)
{
    const int GPB = 8;
    __shared__ float gsh[GPB * 256];
    __shared__ float red[128];
    int tid = threadIdx.x;
    int gbase = blockIdx.x * GPB;

    for (int idx = tid; idx < GPB * 256; idx += 128) {
        int gi = idx >> 8, k = idx & 255;
        int g = gbase + gi;
        int n = (k < 128) ? uidx[g] : iidx[g];
        gsh[idx] = g_h[(long)n * 128 + (k & 127)];
    }
    __syncthreads();

    float acc[GPB];
    float bb = b1[tid];
    #pragma unroll
    for (int gi = 0; gi < GPB; gi++) acc[gi] = bb;

    for (int k = 0; k < 256; k++) {
        float wv = w1[k * 128 + tid];
        #pragma unroll
        for (int gi = 0; gi < GPB; gi++)
            acc[gi] = fmaf(gsh[gi * 256 + k], wv, acc[gi]);
    }

    float w2v = w2[tid];
    float b2v = b2[0];
    #pragma unroll
    for (int gi = 0; gi < GPB; gi++) {
        float z = fmaxf(acc[gi], 0.f) * w2v;
        red[tid] = z;
        __syncthreads();
        for (int o = 64; o > 0; o >>= 1) {
            if (tid < o) red[tid] += red[tid + o];
            __syncthreads();
        }
        if (tid == 0) out[gbase + gi] = red[0] + b2v;
        __syncthreads();
    }
}

// ---------------- launcher ----------------
extern "C" void kernel_launch(void* const* d_in, const int* in_sizes, int n_in,
                              void* d_out, int out_size)
{
    const float* x  = (const float*)d_in[0];
    const int*   ei = (const int*)d_in[1];
    const int*   et = (const int*)d_in[2];
    const int*   ui = (const int*)d_in[3];
    const int*   ii = (const int*)d_in[4];
    const float* basis[4] = {(const float*)d_in[5],  (const float*)d_in[9],
                             (const float*)d_in[13], (const float*)d_in[17]};
    const float* comp[4]  = {(const float*)d_in[6],  (const float*)d_in[10],
                             (const float*)d_in[14], (const float*)d_in[18]};
    const float* root[4]  = {(const float*)d_in[7],  (const float*)d_in[11],
                             (const float*)d_in[15], (const float*)d_in[19]};
    const float* bias[4]  = {(const float*)d_in[8],  (const float*)d_in[12],
                             (const float*)d_in[16], (const float*)d_in[20]};
    const float* w1 = (const float*)d_in[21];
    const float* b1 = (const float*)d_in[22];
    const float* w2 = (const float*)d_in[23];
    const float* b2 = (const float*)d_in[24];
    float* out = (float*)d_out;

    // counting sort by (dst, rel)
    k_build<<<(NE + 255) / 256, 256>>>(ei, et);
    k_scan<<<SCAN_NB, 1024>>>();
    k_scatter<<<(NE + 255) / 256, 256>>>(ei, et);

    // layer 0: input x [N,4]
    k_layer0<<<(NN + 63) / 64, 256>>>(x, basis[0], comp[0], root[0], bias[0]);

    // layers 1..3: 64 nodes/block (8 warps x 8 nodes, groups of 4)
    int lblocks = (NN + 63) / 64;
    k_layer32<<<lblocks, 256>>>(0,  basis[1], comp[1], root[1], bias[1], 32);
    k_layer32<<<lblocks, 256>>>(32, basis[2], comp[2], root[2], bias[2], 64);
    k_layer32<<<lblocks, 256>>>(64, basis[3], comp[3], root[3], bias[3], 96);

    // MLP readout
    k_mlp<<<NG / 8, 128>>>(ui, ii, w1, b1, w2, b2, out);
}

// round 8
// speedup vs baseline: 1.1240x; 1.0335x over previous
#include <cuda_runtime.h>

#define NN 100000
#define NE 3200000
#define NG 4096
#define NRL 5
#define NK (NN*NRL)   // 500000 segments
#define HID 32
#define SCAN_NB ((NK + 1023) / 1024)

// ---------------- scratch (static device globals; no allocation) ----------------
__device__ int   g_cnt[NK];
__device__ int   g_off[NK];
__device__ int   g_cur[NK];
__device__ float g_inv[NK];
__device__ int   g_ssrc[NE];
__device__ float g_h[(long)NN*128];
__device__ int   g_sflag[SCAN_NB];
__device__ int   g_sagg[SCAN_NB];
__device__ int   g_sincl[SCAN_NB];
__device__ int   g_sdone;

// ---------------- build counts ----------------
__global__ void k_build(const int* __restrict__ ei, const int* __restrict__ et) {
    int e = blockIdx.x * blockDim.x + threadIdx.x;
    if (e >= NE) return;
    int d = ei[NE + e];
    int t = et[e];
    atomicAdd(&g_cnt[d * NRL + t], 1);
}

// ---------------- single-pass scan (decoupled lookback) ----------------
__global__ void __launch_bounds__(1024) k_scan() {
    __shared__ int sh[1024];
    __shared__ int s_base;
    __shared__ int s_last;
    int b = blockIdx.x;
    int i = b * 1024 + threadIdx.x;
    int v = (i < NK) ? g_cnt[i] : 0;
    sh[threadIdx.x] = v;
    __syncthreads();
    for (int o = 1; o < 1024; o <<= 1) {
        int t = (threadIdx.x >= o) ? sh[threadIdx.x - o] : 0;
        __syncthreads();
        sh[threadIdx.x] += t;
        __syncthreads();
    }
    int incl_local = sh[threadIdx.x];
    int total = sh[1023];

    if (threadIdx.x == 0) {
        if (b == 0) {
            g_sincl[0] = total;
            __threadfence();
            atomicExch(&g_sflag[0], 2);
            s_base = 0;
        } else {
            g_sagg[b] = total;
            __threadfence();
            atomicExch(&g_sflag[b], 1);
            int p = b - 1;
            int sum = 0;
            while (true) {
                int f;
                do { f = atomicAdd(&g_sflag[p], 0); } while (f == 0);
                __threadfence();
                if (f == 2) { sum += g_sincl[p]; break; }
                sum += g_sagg[p];
                p--;
            }
            s_base = sum;
            g_sincl[b] = sum + total;
            __threadfence();
            atomicExch(&g_sflag[b], 2);
        }
    }
    __syncthreads();
    int base = s_base;
    if (i < NK) {
        int o = base + incl_local - v;
        g_off[i] = o;
        g_cur[i] = o;
        g_inv[i] = 1.0f / (float)(v > 0 ? v : 1);
        g_cnt[i] = 0;   // ready for next replay's k_build
    }
    __syncthreads();
    if (threadIdx.x == 0) {
        __threadfence();
        s_last = (atomicAdd(&g_sdone, 1) == (int)gridDim.x - 1) ? 1 : 0;
    }
    __syncthreads();
    if (s_last) {
        for (int j = threadIdx.x; j < SCAN_NB; j += 1024) g_sflag[j] = 0;
        __syncthreads();
        if (threadIdx.x == 0) { __threadfence(); g_sdone = 0; }
    }
}

// ---------------- scatter (counting-sort pass 2) ----------------
__global__ void k_scatter(const int* __restrict__ ei, const int* __restrict__ et) {
    int e = blockIdx.x * blockDim.x + threadIdx.x;
    if (e >= NE) return;
    int s = ei[e];
    int d = ei[NE + e];
    int t = et[e];
    int k = d * NRL + t;
    int p = atomicAdd(&g_cur[k], 1);
    g_ssrc[p] = s;
}

// ---------------- fused RGCN layer (IN_C = 32) ----------------
// Gather: lane = (edge-subgroup g = lane>>3, quad j = lane&7).
// Each batch covers 4 edges; a lane loads float4 = features [4j,4j+4) of
// edge e+g. Per-relation reduction: 2 shfl levels on the float4.
// Transform: group of 4 nodes, A rows via float4 broadcast, W shared.
__global__ void __launch_bounds__(256) k_layer32(
    int xoff,
    const float* __restrict__ basis, const float* __restrict__ comp,
    const float* __restrict__ root, const float* __restrict__ bias,
    int yoff)
{
    __shared__ float Wsh[160 * 32];                    // 20 KB
    __shared__ __align__(16) float Ash[8][4 * 160];    // 20 KB
    __shared__ float csh[NRL * 4];
    __shared__ float bsh[32];

    int tid = threadIdx.x, w = tid >> 5, lane = tid & 31;
    for (int jj = tid; jj < 128 * 32; jj += 256) Wsh[jj] = basis[jj];
    for (int jj = tid; jj < 32 * 32; jj += 256) Wsh[128 * 32 + jj] = root[jj];
    if (tid < NRL * 4) csh[tid] = comp[tid];
    if (tid < 32) bsh[tid] = bias[tid];
    __syncthreads();

    const float4* __restrict__ Xv = (const float4*)g_h;
    int xoff4 = xoff >> 2;
    int g = lane >> 3, j = lane & 7;

    int nwarp = (blockIdx.x * 8 + w) * 8;              // first node of this warp

    #pragma unroll
    for (int grp = 0; grp < 2; grp++) {
        int nbase = nwarp + grp * 4;

        // ---- gather 4 nodes into Ash[w] ----
        for (int c = 0; c < 4; c++) {
            int n = nbase + c;
            if (n < NN) {   // uniform across warp
                float4 b0 = {0,0,0,0}, b1 = {0,0,0,0}, b2 = {0,0,0,0}, b3 = {0,0,0,0};
                int e0 = g_off[n * NRL];
                #pragma unroll
                for (int r = 0; r < NRL; r++) {
                    int seg = n * NRL + r;
                    int e1 = (seg == NK - 1) ? NE : g_off[seg + 1];
                    float4 f = {0,0,0,0};
                    int e = e0;
                    for (; e + 4 <= e1; e += 4) {
                        int s = g_ssrc[e + g];
                        float4 v = Xv[s * 32 + xoff4 + j];
                        f.x += v.x; f.y += v.y; f.z += v.z; f.w += v.w;
                    }
                    int rem = e1 - e;
                    if (rem > 0) {
                        int ee = e + (g < rem ? g : 0);
                        int s = g_ssrc[ee];
                        float4 v = Xv[s * 32 + xoff4 + j];
                        if (g < rem) {
                            f.x += v.x; f.y += v.y; f.z += v.z; f.w += v.w;
                        }
                    }
                    e0 = e1;
                    // reduce across the 4 edge subgroups (lane offsets 16, 8)
                    f.x += __shfl_down_sync(0xffffffffu, f.x, 16);
                    f.y += __shfl_down_sync(0xffffffffu, f.y, 16);
                    f.z += __shfl_down_sync(0xffffffffu, f.z, 16);
                    f.w += __shfl_down_sync(0xffffffffu, f.w, 16);
                    f.x += __shfl_down_sync(0xffffffffu, f.x, 8);
                    f.y += __shfl_down_sync(0xffffffffu, f.y, 8);
                    f.z += __shfl_down_sync(0xffffffffu, f.z, 8);
                    f.w += __shfl_down_sync(0xffffffffu, f.w, 8);
                    float ivs = g_inv[seg];
                    float4 iv;
                    iv.x = f.x * ivs; iv.y = f.y * ivs; iv.z = f.z * ivs; iv.w = f.w * ivs;
                    float c0 = csh[r * 4 + 0], c1 = csh[r * 4 + 1];
                    float c2 = csh[r * 4 + 2], c3 = csh[r * 4 + 3];
                    b0.x = fmaf(c0, iv.x, b0.x); b0.y = fmaf(c0, iv.y, b0.y);
                    b0.z = fmaf(c0, iv.z, b0.z); b0.w = fmaf(c0, iv.w, b0.w);
                    b1.x = fmaf(c1, iv.x, b1.x); b1.y = fmaf(c1, iv.y, b1.y);
                    b1.z = fmaf(c1, iv.z, b1.z); b1.w = fmaf(c1, iv.w, b1.w);
                    b2.x = fmaf(c2, iv.x, b2.x); b2.y = fmaf(c2, iv.y, b2.y);
                    b2.z = fmaf(c2, iv.z, b2.z); b2.w = fmaf(c2, iv.w, b2.w);
                    b3.x = fmaf(c3, iv.x, b3.x); b3.y = fmaf(c3, iv.y, b3.y);
                    b3.z = fmaf(c3, iv.z, b3.z); b3.w = fmaf(c3, iv.w, b3.w);
                }
                float4 self = Xv[n * 32 + xoff4 + j];
                if (g == 0) {   // lanes 0-7 hold the reduced sums
                    float4* row = (float4*)&Ash[w][c * 160];
                    row[0 * 8 + j] = b0;
                    row[1 * 8 + j] = b1;
                    row[2 * 8 + j] = b2;
                    row[3 * 8 + j] = b3;
                    row[4 * 8 + j] = self;
                }
            }
        }
        __syncwarp();

        // ---- transform group of 4: A via float4 broadcast, W shared ----
        float bb = bsh[lane];
        float acc0 = bb, acc1 = bb, acc2 = bb, acc3 = bb;
        const float4* A0 = (const float4*)&Ash[w][0 * 160];
        const float4* A1 = (const float4*)&Ash[w][1 * 160];
        const float4* A2 = (const float4*)&Ash[w][2 * 160];
        const float4* A3 = (const float4*)&Ash[w][3 * 160];
        #pragma unroll 8
        for (int jv = 0; jv < 40; jv++) {
            float4 u0 = A0[jv];
            float4 u1 = A1[jv];
            float4 u2 = A2[jv];
            float4 u3 = A3[jv];
            const float* wp = &Wsh[jv * 128 + lane];
            float w0 = wp[0], w1 = wp[32], w2 = wp[64], w3 = wp[96];
            acc0 = fmaf(u0.x, w0, acc0); acc1 = fmaf(u1.x, w0, acc1);
            acc2 = fmaf(u2.x, w0, acc2); acc3 = fmaf(u3.x, w0, acc3);
            acc0 = fmaf(u0.y, w1, acc0); acc1 = fmaf(u1.y, w1, acc1);
            acc2 = fmaf(u2.y, w1, acc2); acc3 = fmaf(u3.y, w1, acc3);
            acc0 = fmaf(u0.z, w2, acc0); acc1 = fmaf(u1.z, w2, acc1);
            acc2 = fmaf(u2.z, w2, acc2); acc3 = fmaf(u3.z, w2, acc3);
            acc0 = fmaf(u0.w, w3, acc0); acc1 = fmaf(u1.w, w3, acc1);
            acc2 = fmaf(u2.w, w3, acc2); acc3 = fmaf(u3.w, w3, acc3);
        }
        if (nbase + 0 < NN) g_h[(long)(nbase + 0) * 128 + yoff + lane] = tanhf(acc0);
        if (nbase + 1 < NN) g_h[(long)(nbase + 1) * 128 + yoff + lane] = tanhf(acc1);
        if (nbase + 2 < NN) g_h[(long)(nbase + 2) * 128 + yoff + lane] = tanhf(acc2);
        if (nbase + 3 < NN) g_h[(long)(nbase + 3) * 128 + yoff + lane] = tanhf(acc3);
        __syncwarp();
    }
}

// ---------------- layer 0 (IN_C = 4): 8 edges x 4 features across the warp -----
__global__ void __launch_bounds__(256) k_layer0(
    const float* __restrict__ x,
    const float* __restrict__ basis, const float* __restrict__ comp,
    const float* __restrict__ root, const float* __restrict__ bias)
{
    const int IN_C = 4;
    const int WPB = 8;
    const int NPW = 8;
    __shared__ float Wsh[5 * IN_C * 32];
    __shared__ float csh[NRL * 4];
    __shared__ float bsh[32];
    __shared__ float Ash[WPB][5 * IN_C];

    int tid = threadIdx.x, w = tid >> 5, lane = tid & 31;
    for (int j = tid; j < 4 * IN_C * 32; j += 256) Wsh[j] = basis[j];
    if (tid < IN_C * 32) Wsh[4 * IN_C * 32 + tid] = root[tid];
    if (tid < NRL * 4) csh[tid] = comp[tid];
    if (tid < 32) bsh[tid] = bias[tid];
    __syncthreads();

    int sub  = lane >> 2;   // 0..7 edge subgroup
    int feat = lane & 3;    // 0..3 feature

    int nbase = (blockIdx.x * WPB + w) * NPW;
    for (int ni = 0; ni < NPW; ni++) {
        int n = nbase + ni;
        if (n >= NN) break;   // uniform across warp
        float a0 = 0.f, a1 = 0.f, a2 = 0.f, a3 = 0.f;
        int e0 = g_off[n * NRL];
        #pragma unroll
        for (int r = 0; r < NRL; r++) {
            int seg = n * NRL + r;
            int e1 = (seg == NK - 1) ? NE : g_off[seg + 1];
            float sum = 0.f;
            for (int e = e0 + sub; e < e1; e += 8) {
                int s = g_ssrc[e];
                sum += x[s * 4 + feat];
            }
            e0 = e1;
            sum += __shfl_down_sync(0xffffffffu, sum, 16);
            sum += __shfl_down_sync(0xffffffffu, sum, 8);
            sum += __shfl_down_sync(0xffffffffu, sum, 4);
            if (lane < 4) {
                float iv = g_inv[seg] * sum;
                a0 = fmaf(csh[r * 4 + 0], iv, a0);
                a1 = fmaf(csh[r * 4 + 1], iv, a1);
                a2 = fmaf(csh[r * 4 + 2], iv, a2);
                a3 = fmaf(csh[r * 4 + 3], iv, a3);
            }
        }
        if (lane < 4) {
            Ash[w][0 * IN_C + lane] = a0;
            Ash[w][1 * IN_C + lane] = a1;
            Ash[w][2 * IN_C + lane] = a2;
            Ash[w][3 * IN_C + lane] = a3;
            Ash[w][4 * IN_C + lane] = x[n * 4 + lane];
        }
        __syncwarp();
        float acc = bsh[lane];
        #pragma unroll
        for (int j = 0; j < 5 * IN_C; j++)
            acc = fmaf(Ash[w][j], Wsh[j * 32 + lane], acc);
        g_h[(long)n * 128 + lane] = tanhf(acc);
        __syncwarp();
    }
}

// ---------------- MLP readout ----------------
__global__ void __launch_bounds__(128) k_mlp(
    const int* __restrict__ uidx, const int* __restrict__ iidx,
    const float* __restrict__ w1, const float* __restrict__ b1,
    const float* __restrict__ w2, const float* __restrict__ b2,
    float* __restrict__ out)
{
    const int GPB = 8;
    __shared__ float gsh[GPB * 256];
    __shared__ float red[128];
    int tid = threadIdx.x;
    int gbase = blockIdx.x * GPB;

    for (int idx = tid; idx < GPB * 256; idx += 128) {
        int gi = idx >> 8, k = idx & 255;
        int g = gbase + gi;
        int n = (k < 128) ? uidx[g] : iidx[g];
        gsh[idx] = g_h[(long)n * 128 + (k & 127)];
    }
    __syncthreads();

    float acc[GPB];
    float bb = b1[tid];
    #pragma unroll
    for (int gi = 0; gi < GPB; gi++) acc[gi] = bb;

    for (int k = 0; k < 256; k++) {
        float wv = w1[k * 128 + tid];
        #pragma unroll
        for (int gi = 0; gi < GPB; gi++)
            acc[gi] = fmaf(gsh[gi * 256 + k], wv, acc[gi]);
    }

    float w2v = w2[tid];
    float b2v = b2[0];
    #pragma unroll
    for (int gi = 0; gi < GPB; gi++) {
        float z = fmaxf(acc[gi], 0.f) * w2v;
        red[tid] = z;
        __syncthreads();
        for (int o = 64; o > 0; o >>= 1) {
            if (tid < o) red[tid] += red[tid + o];
            __syncthreads();
        }
        if (tid == 0) out[gbase + gi] = red[0] + b2v;
        __syncthreads();
    }
}

// ---------------- launcher ----------------
extern "C" void kernel_launch(void* const* d_in, const int* in_sizes, int n_in,
                              void* d_out, int out_size)
{
    const float* x  = (const float*)d_in[0];
    const int*   ei = (const int*)d_in[1];
    const int*   et = (const int*)d_in[2];
    const int*   ui = (const int*)d_in[3];
    const int*   ii = (const int*)d_in[4];
    const float* basis[4] = {(const float*)d_in[5],  (const float*)d_in[9],
                             (const float*)d_in[13], (const float*)d_in[17]};
    const float* comp[4]  = {(const float*)d_in[6],  (const float*)d_in[10],
                             (const float*)d_in[14], (const float*)d_in[18]};
    const float* root[4]  = {(const float*)d_in[7],  (const float*)d_in[11],
                             (const float*)d_in[15], (const float*)d_in[19]};
    const float* bias[4]  = {(const float*)d_in[8],  (const float*)d_in[12],
                             (const float*)d_in[16], (const float*)d_in[20]};
    const float* w1 = (const float*)d_in[21];
    const float* b1 = (const float*)d_in[22];
    const float* w2 = (const float*)d_in[23];
    const float* b2 = (const float*)d_in[24];
    float* out = (float*)d_out;

    // counting sort by (dst, rel)
    k_build<<<(NE + 255) / 256, 256>>>(ei, et);
    k_scan<<<SCAN_NB, 1024>>>();
    k_scatter<<<(NE + 255) / 256, 256>>>(ei, et);

    // layer 0: input x [N,4]
    k_layer0<<<(NN + 63) / 64, 256>>>(x, basis[0], comp[0], root[0], bias[0]);

    // layers 1..3: 64 nodes/block (8 warps x 8 nodes, groups of 4)
    int lblocks = (NN + 63) / 64;
    k_layer32<<<lblocks, 256>>>(0,  basis[1], comp[1], root[1], bias[1], 32);
    k_layer32<<<lblocks, 256>>>(32, basis[2], comp[2], root[2], bias[2], 64);
    k_layer32<<<lblocks, 256>>>(64, basis[3], comp[3], root[3], bias[3], 96);

    // MLP readout
    k_mlp<<<NG / 8, 128>>>(ui, ii, w1, b1, w2, b2, out);
}

// round 9
// speedup vs baseline: 1.1443x; 1.0180x over previous
#include <cuda_runtime.h>

#define NN 100000
#define NE 3200000
#define NG 4096
#define NRL 5
#define NK (NN*NRL)   // 500000 segments
#define HID 32
#define SCAN_NB ((NK + 1023) / 1024)

// ---------------- scratch (static device globals; no allocation) ----------------
__device__ int   g_cnt[NK];
__device__ int   g_off[NK];
__device__ int   g_cur[NK];
__device__ float g_inv[NK];
__device__ int   g_ssrc[NE];
__device__ float g_h[(long)NN*128];
__device__ int   g_sflag[SCAN_NB];
__device__ int   g_sagg[SCAN_NB];
__device__ int   g_sincl[SCAN_NB];
__device__ int   g_sdone;

// ---------------- build counts ----------------
__global__ void k_build(const int* __restrict__ ei, const int* __restrict__ et) {
    int e = blockIdx.x * blockDim.x + threadIdx.x;
    if (e >= NE) return;
    int d = ei[NE + e];
    int t = et[e];
    atomicAdd(&g_cnt[d * NRL + t], 1);
}

// ---------------- single-pass scan (decoupled lookback) ----------------
__global__ void __launch_bounds__(1024) k_scan() {
    __shared__ int sh[1024];
    __shared__ int s_base;
    __shared__ int s_last;
    int b = blockIdx.x;
    int i = b * 1024 + threadIdx.x;
    int v = (i < NK) ? g_cnt[i] : 0;
    sh[threadIdx.x] = v;
    __syncthreads();
    for (int o = 1; o < 1024; o <<= 1) {
        int t = (threadIdx.x >= o) ? sh[threadIdx.x - o] : 0;
        __syncthreads();
        sh[threadIdx.x] += t;
        __syncthreads();
    }
    int incl_local = sh[threadIdx.x];
    int total = sh[1023];

    if (threadIdx.x == 0) {
        if (b == 0) {
            g_sincl[0] = total;
            __threadfence();
            atomicExch(&g_sflag[0], 2);
            s_base = 0;
        } else {
            g_sagg[b] = total;
            __threadfence();
            atomicExch(&g_sflag[b], 1);
            int p = b - 1;
            int sum = 0;
            while (true) {
                int f;
                do { f = atomicAdd(&g_sflag[p], 0); } while (f == 0);
                __threadfence();
                if (f == 2) { sum += g_sincl[p]; break; }
                sum += g_sagg[p];
                p--;
            }
            s_base = sum;
            g_sincl[b] = sum + total;
            __threadfence();
            atomicExch(&g_sflag[b], 2);
        }
    }
    __syncthreads();
    int base = s_base;
    if (i < NK) {
        int o = base + incl_local - v;
        g_off[i] = o;
        g_cur[i] = o;
        g_inv[i] = 1.0f / (float)(v > 0 ? v : 1);
        g_cnt[i] = 0;   // ready for next replay's k_build
    }
    __syncthreads();
    if (threadIdx.x == 0) {
        __threadfence();
        s_last = (atomicAdd(&g_sdone, 1) == (int)gridDim.x - 1) ? 1 : 0;
    }
    __syncthreads();
    if (s_last) {
        for (int j = threadIdx.x; j < SCAN_NB; j += 1024) g_sflag[j] = 0;
        __syncthreads();
        if (threadIdx.x == 0) { __threadfence(); g_sdone = 0; }
    }
}

// ---------------- scatter (counting-sort pass 2) ----------------
__global__ void k_scatter(const int* __restrict__ ei, const int* __restrict__ et) {
    int e = blockIdx.x * blockDim.x + threadIdx.x;
    if (e >= NE) return;
    int s = ei[e];
    int d = ei[NE + e];
    int t = et[e];
    int k = d * NRL + t;
    int p = atomicAdd(&g_cur[k], 1);
    g_ssrc[p] = s;
}

// ---------------- fused RGCN layer (IN_C = 32) — R3 structure ----------------
// 8 warps x 8 nodes, lane = feature. Per node: unrolled edge gather with 4
// independent accumulators (high MLP), then 160-row transform with A read
// as broadcast LDS.128 (4 rows per load) and W as scalar LDS.
__global__ void __launch_bounds__(256) k_layer32(
    int xoff,
    const float* __restrict__ basis, const float* __restrict__ comp,
    const float* __restrict__ root, const float* __restrict__ bias,
    int yoff)
{
    const int IN_C = 32;
    const int WPB = 8;   // warps per block
    const int NPW = 8;   // nodes per warp
    __shared__ float Wsh[5 * IN_C * 32];
    __shared__ float csh[NRL * 4];
    __shared__ float bsh[32];
    __shared__ __align__(16) float Ash[WPB][5 * IN_C];

    int tid = threadIdx.x, w = tid >> 5, lane = tid & 31;
    for (int j = tid; j < 4 * IN_C * 32; j += 256) Wsh[j] = basis[j];
    for (int j = tid; j < IN_C * 32; j += 256) Wsh[4 * IN_C * 32 + j] = root[j];
    if (tid < NRL * 4) csh[tid] = comp[tid];
    if (tid < 32) bsh[tid] = bias[tid];
    __syncthreads();

    const float* __restrict__ X = g_h + xoff + lane;   // per-lane feature column

    int nbase = (blockIdx.x * WPB + w) * NPW;
    for (int ni = 0; ni < NPW; ni++) {
        int n = nbase + ni;
        if (n >= NN) break;   // uniform across warp
        float a0 = 0.f, a1 = 0.f, a2 = 0.f, a3 = 0.f;
        int e0 = g_off[n * NRL];
        #pragma unroll
        for (int r = 0; r < NRL; r++) {
            int seg = n * NRL + r;
            int e1 = (seg == NK - 1) ? NE : g_off[seg + 1];
            float s0 = 0.f, s1 = 0.f, s2 = 0.f, s3 = 0.f;
            int e = e0;
            for (; e + 3 < e1; e += 4) {
                int ia = g_ssrc[e + 0];
                int ib = g_ssrc[e + 1];
                int ic = g_ssrc[e + 2];
                int id = g_ssrc[e + 3];
                s0 += X[ia * 128];
                s1 += X[ib * 128];
                s2 += X[ic * 128];
                s3 += X[id * 128];
            }
            for (; e < e1; e++) s0 += X[g_ssrc[e] * 128];
            e0 = e1;
            float iv = g_inv[seg] * ((s0 + s1) + (s2 + s3));
            a0 = fmaf(csh[r * 4 + 0], iv, a0);
            a1 = fmaf(csh[r * 4 + 1], iv, a1);
            a2 = fmaf(csh[r * 4 + 2], iv, a2);
            a3 = fmaf(csh[r * 4 + 3], iv, a3);
        }
        Ash[w][0 * IN_C + lane] = a0;
        Ash[w][1 * IN_C + lane] = a1;
        Ash[w][2 * IN_C + lane] = a2;
        Ash[w][3 * IN_C + lane] = a3;
        Ash[w][4 * IN_C + lane] = X[n * 128];
        __syncwarp();
        // transform: A via broadcast LDS.128 (4 rows/load), W scalar LDS
        float acc = bsh[lane];
        const float4* Av = (const float4*)&Ash[w][0];   // 40 float4s
        #pragma unroll 8
        for (int jv = 0; jv < 40; jv++) {
            float4 a4 = Av[jv];
            const float* wp = &Wsh[jv * 128 + lane];
            acc = fmaf(a4.x, wp[0],  acc);
            acc = fmaf(a4.y, wp[32], acc);
            acc = fmaf(a4.z, wp[64], acc);
            acc = fmaf(a4.w, wp[96], acc);
        }
        g_h[(long)n * 128 + yoff + lane] = tanhf(acc);
        __syncwarp();
    }
}

// ---------------- layer 0 (IN_C = 4): 8 edges x 4 features across the warp -----
__global__ void __launch_bounds__(256) k_layer0(
    const float* __restrict__ x,
    const float* __restrict__ basis, const float* __restrict__ comp,
    const float* __restrict__ root, const float* __restrict__ bias)
{
    const int IN_C = 4;
    const int WPB = 8;
    const int NPW = 8;
    __shared__ float Wsh[5 * IN_C * 32];
    __shared__ float csh[NRL * 4];
    __shared__ float bsh[32];
    __shared__ float Ash[WPB][5 * IN_C];

    int tid = threadIdx.x, w = tid >> 5, lane = tid & 31;
    for (int j = tid; j < 4 * IN_C * 32; j += 256) Wsh[j] = basis[j];
    if (tid < IN_C * 32) Wsh[4 * IN_C * 32 + tid] = root[tid];
    if (tid < NRL * 4) csh[tid] = comp[tid];
    if (tid < 32) bsh[tid] = bias[tid];
    __syncthreads();

    int sub  = lane >> 2;   // 0..7 edge subgroup
    int feat = lane & 3;    // 0..3 feature

    int nbase = (blockIdx.x * WPB + w) * NPW;
    for (int ni = 0; ni < NPW; ni++) {
        int n = nbase + ni;
        if (n >= NN) break;   // uniform across warp
        float a0 = 0.f, a1 = 0.f, a2 = 0.f, a3 = 0.f;
        int e0 = g_off[n * NRL];
        #pragma unroll
        for (int r = 0; r < NRL; r++) {
            int seg = n * NRL + r;
            int e1 = (seg == NK - 1) ? NE : g_off[seg + 1];
            float sum = 0.f;
            for (int e = e0 + sub; e < e1; e += 8) {
                int s = g_ssrc[e];
                sum += x[s * 4 + feat];
            }
            e0 = e1;
            sum += __shfl_down_sync(0xffffffffu, sum, 16);
            sum += __shfl_down_sync(0xffffffffu, sum, 8);
            sum += __shfl_down_sync(0xffffffffu, sum, 4);
            if (lane < 4) {
                float iv = g_inv[seg] * sum;
                a0 = fmaf(csh[r * 4 + 0], iv, a0);
                a1 = fmaf(csh[r * 4 + 1], iv, a1);
                a2 = fmaf(csh[r * 4 + 2], iv, a2);
                a3 = fmaf(csh[r * 4 + 3], iv, a3);
            }
        }
        if (lane < 4) {
            Ash[w][0 * IN_C + lane] = a0;
            Ash[w][1 * IN_C + lane] = a1;
            Ash[w][2 * IN_C + lane] = a2;
            Ash[w][3 * IN_C + lane] = a3;
            Ash[w][4 * IN_C + lane] = x[n * 4 + lane];
        }
        __syncwarp();
        float acc = bsh[lane];
        #pragma unroll
        for (int j = 0; j < 5 * IN_C; j++)
            acc = fmaf(Ash[w][j], Wsh[j * 32 + lane], acc);
        g_h[(long)n * 128 + lane] = tanhf(acc);
        __syncwarp();
    }
}

// ---------------- MLP readout ----------------
__global__ void __launch_bounds__(128) k_mlp(
    const int* __restrict__ uidx, const int* __restrict__ iidx,
    const float* __restrict__ w1, const float* __restrict__ b1,
    const float* __restrict__ w2, const float* __restrict__ b2,
    float* __restrict__ out)
{
    const int GPB = 8;
    __shared__ float gsh[GPB * 256];
    __shared__ float red[128];
    int tid = threadIdx.x;
    int gbase = blockIdx.x * GPB;

    for (int idx = tid; idx < GPB * 256; idx += 128) {
        int gi = idx >> 8, k = idx & 255;
        int g = gbase + gi;
        int n = (k < 128) ? uidx[g] : iidx[g];
        gsh[idx] = g_h[(long)n * 128 + (k & 127)];
    }
    __syncthreads();

    float acc[GPB];
    float bb = b1[tid];
    #pragma unroll
    for (int gi = 0; gi < GPB; gi++) acc[gi] = bb;

    for (int k = 0; k < 256; k++) {
        float wv = w1[k * 128 + tid];
        #pragma unroll
        for (int gi = 0; gi < GPB; gi++)
            acc[gi] = fmaf(gsh[gi * 256 + k], wv, acc[gi]);
    }

    float w2v = w2[tid];
    float b2v = b2[0];
    #pragma unroll
    for (int gi = 0; gi < GPB; gi++) {
        float z = fmaxf(acc[gi], 0.f) * w2v;
        red[tid] = z;
        __syncthreads();
        for (int o = 64; o > 0; o >>= 1) {
            if (tid < o) red[tid] += red[tid + o];
            __syncthreads();
        }
        if (tid == 0) out[gbase + gi] = red[0] + b2v;
        __syncthreads();
    }
}

// ---------------- launcher ----------------
extern "C" void kernel_launch(void* const* d_in, const int* in_sizes, int n_in,
                              void* d_out, int out_size)
{
    const float* x  = (const float*)d_in[0];
    const int*   ei = (const int*)d_in[1];
    const int*   et = (const int*)d_in[2];
    const int*   ui = (const int*)d_in[3];
    const int*   ii = (const int*)d_in[4];
    const float* basis[4] = {(const float*)d_in[5],  (const float*)d_in[9],
                             (const float*)d_in[13], (const float*)d_in[17]};
    const float* comp[4]  = {(const float*)d_in[6],  (const float*)d_in[10],
                             (const float*)d_in[14], (const float*)d_in[18]};
    const float* root[4]  = {(const float*)d_in[7],  (const float*)d_in[11],
                             (const float*)d_in[15], (const float*)d_in[19]};
    const float* bias[4]  = {(const float*)d_in[8],  (const float*)d_in[12],
                             (const float*)d_in[16], (const float*)d_in[20]};
    const float* w1 = (const float*)d_in[21];
    const float* b1 = (const float*)d_in[22];
    const float* w2 = (const float*)d_in[23];
    const float* b2 = (const float*)d_in[24];
    float* out = (float*)d_out;

    // counting sort by (dst, rel)
    k_build<<<(NE + 255) / 256, 256>>>(ei, et);
    k_scan<<<SCAN_NB, 1024>>>();
    k_scatter<<<(NE + 255) / 256, 256>>>(ei, et);

    // layer 0: input x [N,4]
    k_layer0<<<(NN + 63) / 64, 256>>>(x, basis[0], comp[0], root[0], bias[0]);

    // layers 1..3: 64 nodes/block (8 warps x 8 nodes)
    int lblocks = (NN + 63) / 64;
    k_layer32<<<lblocks, 256>>>(0,  basis[1], comp[1], root[1], bias[1], 32);
    k_layer32<<<lblocks, 256>>>(32, basis[2], comp[2], root[2], bias[2], 64);
    k_layer32<<<lblocks, 256>>>(64, basis[3], comp[3], root[3], bias[3], 96);

    // MLP readout
    k_mlp<<<NG / 8, 128>>>(ui, ii, w1, b1, w2, b2, out);
}

// round 10
// speedup vs baseline: 1.2146x; 1.0615x over previous
#include <cuda_runtime.h>

#define NN 100000
#define NE 3200000
#define NG 4096
#define NRL 5
#define NK (NN*NRL)   // 500000 segments
#define HID 32

// ---------------- scratch (static device globals; no allocation) ----------------
__device__ int   g_cnt[NK];      // zero-initialized; re-zeroed by k_scanC each run
__device__ int   g_off[NK];
__device__ int   g_cur[NK];
__device__ float g_inv[NK];
__device__ int   g_ssrc[NE];
__device__ int   g_bsum[512];
__device__ int   g_bsumex[512];
__device__ float g_h[(long)NN*128];

// ---------------- build counts ----------------
__global__ void k_build(const int* __restrict__ ei, const int* __restrict__ et) {
    int e = blockIdx.x * blockDim.x + threadIdx.x;
    if (e >= NE) return;
    int d = ei[NE + e];
    int t = et[e];
    atomicAdd(&g_cnt[d * NRL + t], 1);
}

// ---------------- 3-kernel scan (proven) ----------------
__global__ void k_scanA() {
    __shared__ int sh[1024];
    int i = blockIdx.x * 1024 + threadIdx.x;
    int v = (i < NK) ? g_cnt[i] : 0;
    sh[threadIdx.x] = v;
    __syncthreads();
    for (int o = 1; o < 1024; o <<= 1) {
        int t = (threadIdx.x >= o) ? sh[threadIdx.x - o] : 0;
        __syncthreads();
        sh[threadIdx.x] += t;
        __syncthreads();
    }
    if (i < NK) g_off[i] = sh[threadIdx.x] - v;   // exclusive within block
    if (threadIdx.x == 1023) g_bsum[blockIdx.x] = sh[1023];
}

__global__ void k_scanB(int nb) {
    __shared__ int sh[512];
    int v = (threadIdx.x < nb) ? g_bsum[threadIdx.x] : 0;
    sh[threadIdx.x] = v;
    __syncthreads();
    for (int o = 1; o < 512; o <<= 1) {
        int t = (threadIdx.x >= o) ? sh[threadIdx.x - o] : 0;
        __syncthreads();
        sh[threadIdx.x] += t;
        __syncthreads();
    }
    g_bsumex[threadIdx.x] = sh[threadIdx.x] - v;
}

__global__ void k_scanC() {
    int i = blockIdx.x * blockDim.x + threadIdx.x;
    if (i >= NK) return;
    int o = g_off[i] + g_bsumex[i >> 10];
    g_off[i] = o;
    g_cur[i] = o;
    int c = g_cnt[i];
    g_inv[i] = 1.0f / (float)(c > 0 ? c : 1);
    g_cnt[i] = 0;   // ready for next replay's k_build
}

// ---------------- scatter (counting-sort pass 2) ----------------
__global__ void k_scatter(const int* __restrict__ ei, const int* __restrict__ et) {
    int e = blockIdx.x * blockDim.x + threadIdx.x;
    if (e >= NE) return;
    int s = ei[e];
    int d = ei[NE + e];
    int t = et[e];
    int k = d * NRL + t;
    int p = atomicAdd(&g_cur[k], 1);
    g_ssrc[p] = s;
}

// ---------------- fused RGCN layer (IN_C = 32) ----------------
// 8 warps x 8 nodes, lane = feature. Per node: unrolled edge gather with 4
// independent accumulators (high MLP), then 160-row transform with A read
// as broadcast LDS.128 (4 rows per load) and W as scalar LDS.
__global__ void __launch_bounds__(256) k_layer32(
    int xoff,
    const float* __restrict__ basis, const float* __restrict__ comp,
    const float* __restrict__ root, const float* __restrict__ bias,
    int yoff)
{
    const int IN_C = 32;
    const int WPB = 8;   // warps per block
    const int NPW = 8;   // nodes per warp
    __shared__ float Wsh[5 * IN_C * 32];
    __shared__ float csh[NRL * 4];
    __shared__ float bsh[32];
    __shared__ __align__(16) float Ash[WPB][5 * IN_C];

    int tid = threadIdx.x, w = tid >> 5, lane = tid & 31;
    for (int j = tid; j < 4 * IN_C * 32; j += 256) Wsh[j] = basis[j];
    for (int j = tid; j < IN_C * 32; j += 256) Wsh[4 * IN_C * 32 + j] = root[j];
    if (tid < NRL * 4) csh[tid] = comp[tid];
    if (tid < 32) bsh[tid] = bias[tid];
    __syncthreads();

    const float* __restrict__ X = g_h + xoff + lane;   // per-lane feature column

    int nbase = (blockIdx.x * WPB + w) * NPW;
    for (int ni = 0; ni < NPW; ni++) {
        int n = nbase + ni;
        if (n >= NN) break;   // uniform across warp
        float a0 = 0.f, a1 = 0.f, a2 = 0.f, a3 = 0.f;
        int e0 = g_off[n * NRL];
        #pragma unroll
        for (int r = 0; r < NRL; r++) {
            int seg = n * NRL + r;
            int e1 = (seg == NK - 1) ? NE : g_off[seg + 1];
            float s0 = 0.f, s1 = 0.f, s2 = 0.f, s3 = 0.f;
            int e = e0;
            for (; e + 3 < e1; e += 4) {
                int ia = g_ssrc[e + 0];
                int ib = g_ssrc[e + 1];
                int ic = g_ssrc[e + 2];
                int id = g_ssrc[e + 3];
                s0 += X[ia * 128];
                s1 += X[ib * 128];
                s2 += X[ic * 128];
                s3 += X[id * 128];
            }
            for (; e < e1; e++) s0 += X[g_ssrc[e] * 128];
            e0 = e1;
            float iv = g_inv[seg] * ((s0 + s1) + (s2 + s3));
            a0 = fmaf(csh[r * 4 + 0], iv, a0);
            a1 = fmaf(csh[r * 4 + 1], iv, a1);
            a2 = fmaf(csh[r * 4 + 2], iv, a2);
            a3 = fmaf(csh[r * 4 + 3], iv, a3);
        }
        Ash[w][0 * IN_C + lane] = a0;
        Ash[w][1 * IN_C + lane] = a1;
        Ash[w][2 * IN_C + lane] = a2;
        Ash[w][3 * IN_C + lane] = a3;
        Ash[w][4 * IN_C + lane] = X[n * 128];
        __syncwarp();
        // transform: A via broadcast LDS.128 (4 rows/load), W scalar LDS
        float acc = bsh[lane];
        const float4* Av = (const float4*)&Ash[w][0];   // 40 float4s
        #pragma unroll 8
        for (int jv = 0; jv < 40; jv++) {
            float4 a4 = Av[jv];
            const float* wp = &Wsh[jv * 128 + lane];
            acc = fmaf(a4.x, wp[0],  acc);
            acc = fmaf(a4.y, wp[32], acc);
            acc = fmaf(a4.z, wp[64], acc);
            acc = fmaf(a4.w, wp[96], acc);
        }
        g_h[(long)n * 128 + yoff + lane] = tanhf(acc);
        __syncwarp();
    }
}

// ---------------- layer 0 (IN_C = 4): 8 edges x 4 features across the warp -----
__global__ void __launch_bounds__(256) k_layer0(
    const float* __restrict__ x,
    const float* __restrict__ basis, const float* __restrict__ comp,
    const float* __restrict__ root, const float* __restrict__ bias)
{
    const int IN_C = 4;
    const int WPB = 8;
    const int NPW = 8;
    __shared__ float Wsh[5 * IN_C * 32];
    __shared__ float csh[NRL * 4];
    __shared__ float bsh[32];
    __shared__ float Ash[WPB][5 * IN_C];

    int tid = threadIdx.x, w = tid >> 5, lane = tid & 31;
    for (int j = tid; j < 4 * IN_C * 32; j += 256) Wsh[j] = basis[j];
    if (tid < IN_C * 32) Wsh[4 * IN_C * 32 + tid] = root[tid];
    if (tid < NRL * 4) csh[tid] = comp[tid];
    if (tid < 32) bsh[tid] = bias[tid];
    __syncthreads();

    int sub  = lane >> 2;   // 0..7 edge subgroup
    int feat = lane & 3;    // 0..3 feature

    int nbase = (blockIdx.x * WPB + w) * NPW;
    for (int ni = 0; ni < NPW; ni++) {
        int n = nbase + ni;
        if (n >= NN) break;   // uniform across warp
        float a0 = 0.f, a1 = 0.f, a2 = 0.f, a3 = 0.f;
        int e0 = g_off[n * NRL];
        #pragma unroll
        for (int r = 0; r < NRL; r++) {
            int seg = n * NRL + r;
            int e1 = (seg == NK - 1) ? NE : g_off[seg + 1];
            float sum = 0.f;
            for (int e = e0 + sub; e < e1; e += 8) {
                int s = g_ssrc[e];
                sum += x[s * 4 + feat];
            }
            e0 = e1;
            sum += __shfl_down_sync(0xffffffffu, sum, 16);
            sum += __shfl_down_sync(0xffffffffu, sum, 8);
            sum += __shfl_down_sync(0xffffffffu, sum, 4);
            if (lane < 4) {
                float iv = g_inv[seg] * sum;
                a0 = fmaf(csh[r * 4 + 0], iv, a0);
                a1 = fmaf(csh[r * 4 + 1], iv, a1);
                a2 = fmaf(csh[r * 4 + 2], iv, a2);
                a3 = fmaf(csh[r * 4 + 3], iv, a3);
            }
        }
        if (lane < 4) {
            Ash[w][0 * IN_C + lane] = a0;
            Ash[w][1 * IN_C + lane] = a1;
            Ash[w][2 * IN_C + lane] = a2;
            Ash[w][3 * IN_C + lane] = a3;
            Ash[w][4 * IN_C + lane] = x[n * 4 + lane];
        }
        __syncwarp();
        float acc = bsh[lane];
        #pragma unroll
        for (int j = 0; j < 5 * IN_C; j++)
            acc = fmaf(Ash[w][j], Wsh[j * 32 + lane], acc);
        g_h[(long)n * 128 + lane] = tanhf(acc);
        __syncwarp();
    }
}

// ---------------- MLP readout ----------------
__global__ void __launch_bounds__(128) k_mlp(
    const int* __restrict__ uidx, const int* __restrict__ iidx,
    const float* __restrict__ w1, const float* __restrict__ b1,
    const float* __restrict__ w2, const float* __restrict__ b2,
    float* __restrict__ out)
{
    const int GPB = 8;
    __shared__ float gsh[GPB * 256];
    __shared__ float red[128];
    int tid = threadIdx.x;
    int gbase = blockIdx.x * GPB;

    for (int idx = tid; idx < GPB * 256; idx += 128) {
        int gi = idx >> 8, k = idx & 255;
        int g = gbase + gi;
        int n = (k < 128) ? uidx[g] : iidx[g];
        gsh[idx] = g_h[(long)n * 128 + (k & 127)];
    }
    __syncthreads();

    float acc[GPB];
    float bb = b1[tid];
    #pragma unroll
    for (int gi = 0; gi < GPB; gi++) acc[gi] = bb;

    for (int k = 0; k < 256; k++) {
        float wv = w1[k * 128 + tid];
        #pragma unroll
        for (int gi = 0; gi < GPB; gi++)
            acc[gi] = fmaf(gsh[gi * 256 + k], wv, acc[gi]);
    }

    float w2v = w2[tid];
    float b2v = b2[0];
    #pragma unroll
    for (int gi = 0; gi < GPB; gi++) {
        float z = fmaxf(acc[gi], 0.f) * w2v;
        red[tid] = z;
        __syncthreads();
        for (int o = 64; o > 0; o >>= 1) {
            if (tid < o) red[tid] += red[tid + o];
            __syncthreads();
        }
        if (tid == 0) out[gbase + gi] = red[0] + b2v;
        __syncthreads();
    }
}

// ---------------- launcher ----------------
extern "C" void kernel_launch(void* const* d_in, const int* in_sizes, int n_in,
                              void* d_out, int out_size)
{
    const float* x  = (const float*)d_in[0];
    const int*   ei = (const int*)d_in[1];
    const int*   et = (const int*)d_in[2];
    const int*   ui = (const int*)d_in[3];
    const int*   ii = (const int*)d_in[4];
    const float* basis[4] = {(const float*)d_in[5],  (const float*)d_in[9],
                             (const float*)d_in[13], (const float*)d_in[17]};
    const float* comp[4]  = {(const float*)d_in[6],  (const float*)d_in[10],
                             (const float*)d_in[14], (const float*)d_in[18]};
    const float* root[4]  = {(const float*)d_in[7],  (const float*)d_in[11],
                             (const float*)d_in[15], (const float*)d_in[19]};
    const float* bias[4]  = {(const float*)d_in[8],  (const float*)d_in[12],
                             (const float*)d_in[16], (const float*)d_in[20]};
    const float* w1 = (const float*)d_in[21];
    const float* b1 = (const float*)d_in[22];
    const float* w2 = (const float*)d_in[23];
    const float* b2 = (const float*)d_in[24];
    float* out = (float*)d_out;

    // counting sort by (dst, rel): g_cnt starts zero (static init on run 1,
    // re-zeroed by k_scanC for subsequent graph replays)
    k_build<<<(NE + 255) / 256, 256>>>(ei, et);
    k_scanA<<<(NK + 1023) / 1024, 1024>>>();
    k_scanB<<<1, 512>>>((NK + 1023) / 1024);
    k_scanC<<<(NK + 255) / 256, 256>>>();
    k_scatter<<<(NE + 255) / 256, 256>>>(ei, et);

    // layer 0: input x [N,4]
    k_layer0<<<(NN + 63) / 64, 256>>>(x, basis[0], comp[0], root[0], bias[0]);

    // layers 1..3: 64 nodes/block (8 warps x 8 nodes)
    int lblocks = (NN + 63) / 64;
    k_layer32<<<lblocks, 256>>>(0,  basis[1], comp[1], root[1], bias[1], 32);
    k_layer32<<<lblocks, 256>>>(32, basis[2], comp[2], root[2], bias[2], 64);
    k_layer32<<<lblocks, 256>>>(64, basis[3], comp[3], root[3], bias[3], 96);

    // MLP readout
    k_mlp<<<NG / 8, 128>>>(ui, ii, w1, b1, w2, b2, out);
}